// round 10
// baseline (speedup 1.0000x reference)
#include <cuda_runtime.h>

// ContrastivePredictionLoss — two-kernel, R10 (verbatim retry of R9 after
// broker/container infra failure; same kernel passed-pattern as R2->R3, R7->R8).
//
// Stage A: 1024 blocks (16/batch) x 256 thr — fits in one wave (148 SMs x ~8
//          blocks) instead of R6's 2048 blocks = 1.73 waves. Loop body per
//          iteration identical to the proven 6.2 TB/s body; only trip count
//          and grid shape change (isolates wave-quantization effect).
// Stage B: R6's cooperative float4 finalize (5.8us), plain launch (PDL was
//          measured neutral in R8 and removed).

#define NB 64
#define ELEMS_PER_BATCH (4 * 256 * 256)      // 262144
#define BLOCKS_PER_BATCH 16
#define NBLOCKS (NB * BLOCKS_PER_BATCH)      // 1024
#define THREADS_A 256
#define ELEMS_PER_BLOCK (ELEMS_PER_BATCH / BLOCKS_PER_BATCH)   // 16384
#define VECS_PER_BLOCK (ELEMS_PER_BLOCK / 4)                   // 4096 float4
#define VECS_PER_THREAD (VECS_PER_BLOCK / THREADS_A)           // 16

// Scratch (allocation-free __device__ global). x = err partial, y = unc partial.
__device__ float2 g_part[NBLOCKS];

__global__ __launch_bounds__(THREADS_A)
void cpl_reduce_kernel(const float4* __restrict__ pm,
                       const float4* __restrict__ ps,
                       const float4* __restrict__ tg) {
    const int blk = blockIdx.x;                      // b * 16 + chunk
    const int tid = threadIdx.x;
    const long base = (long)blk * VECS_PER_BLOCK;

    float se = 0.0f;   // sum |pm - tg|
    float su = 0.0f;   // sum ps

    #pragma unroll
    for (int i = 0; i < VECS_PER_THREAD; i++) {
        const long idx = base + (long)i * THREADS_A + tid;
        float4 m = pm[idx];
        float4 t = tg[idx];
        float4 s = ps[idx];
        se += fabsf(m.x - t.x) + fabsf(m.y - t.y)
            + fabsf(m.z - t.z) + fabsf(m.w - t.w);
        su += s.x + s.y + s.z + s.w;
    }

    // Warp reduce (deterministic shuffle tree)
    #pragma unroll
    for (int off = 16; off > 0; off >>= 1) {
        se += __shfl_down_sync(0xFFFFFFFFu, se, off);
        su += __shfl_down_sync(0xFFFFFFFFu, su, off);
    }

    __shared__ float s_se[THREADS_A / 32];
    __shared__ float s_su[THREADS_A / 32];
    const int wid = tid >> 5;
    const int lid = tid & 31;
    if (lid == 0) { s_se[wid] = se; s_su[wid] = su; }
    __syncthreads();

    if (wid == 0) {
        se = (lid < THREADS_A / 32) ? s_se[lid] : 0.0f;
        su = (lid < THREADS_A / 32) ? s_su[lid] : 0.0f;
        #pragma unroll
        for (int off = 4; off > 0; off >>= 1) {
            se += __shfl_down_sync(0xFFFFFFFFu, se, off);
            su += __shfl_down_sync(0xFFFFFFFFu, su, off);
        }
        if (lid == 0) {
            g_part[blk] = make_float2(se, su);
        }
    }
}

#define THREADS_B 256

__global__ __launch_bounds__(THREADS_B)
void cpl_finalize_kernel(float* __restrict__ out) {
    const int tid = threadIdx.x;
    const int wid = tid >> 5;
    const int lid = tid & 31;

    // 1024 float2 partials = 512 float4. Batch b occupies float4 indices
    // [b*8, b*8+8). Thread -> b = tid>>2, quarter q = tid&3: 2 float4 each.
    const int b = tid >> 2;
    const int q = tid & 3;
    const float4* p4 = (const float4*)g_part;

    float4 v0 = p4[b * 8 + q * 2 + 0];   // {err,unc,err,unc}
    float4 v1 = p4[b * 8 + q * 2 + 1];
    float pe = (v0.x + v0.z) + (v1.x + v1.z);
    float pu = (v0.y + v0.w) + (v1.y + v1.w);

    __shared__ float s_pe[4][NB];
    __shared__ float s_pu[4][NB];
    s_pe[q][b] = pe;
    s_pu[q][b] = pu;
    __syncthreads();

    __shared__ float errs[NB];
    __shared__ float uncs[NB];
    if (tid < NB) {
        const float inv = 1.0f / (float)ELEMS_PER_BATCH;
        errs[tid] = ((s_pe[0][tid] + s_pe[1][tid]) + (s_pe[2][tid] + s_pe[3][tid])) * inv;
        uncs[tid] = ((s_pu[0][tid] + s_pu[1][tid]) + (s_pu[2][tid] + s_pu[3][tid])) * inv;
    }
    __syncthreads();

    // Pairwise hinge over upper triangle (i < j), fixed iteration order.
    float acc = 0.0f;
    #pragma unroll
    for (int p = tid; p < NB * NB; p += THREADS_B) {
        const int i = p >> 6;
        const int j = p & 63;
        if (i < j) {
            const float d = ((errs[i] > errs[j]) ? (uncs[j] - uncs[i])
                                                 : (uncs[i] - uncs[j])) + 1.0f;
            acc += fmaxf(d, 0.0f);
        }
    }

    #pragma unroll
    for (int off = 16; off > 0; off >>= 1)
        acc += __shfl_down_sync(0xFFFFFFFFu, acc, off);

    __shared__ float s_acc[THREADS_B / 32];
    if (lid == 0) s_acc[wid] = acc;
    __syncthreads();

    if (tid == 0) {
        float total = 0.0f;
        #pragma unroll
        for (int w = 0; w < THREADS_B / 32; w++) total += s_acc[w];
        const int num_pairs = NB * (NB - 1) / 2;   // 2016
        out[0] = total / (float)num_pairs;
    }
}

extern "C" void kernel_launch(void* const* d_in, const int* in_sizes, int n_in,
                              void* d_out, int out_size) {
    const float4* pm = (const float4*)d_in[0];   // pred_mean
    const float4* ps = (const float4*)d_in[1];   // pred_std
    const float4* tg = (const float4*)d_in[2];   // targets
    float* out = (float*)d_out;

    cpl_reduce_kernel<<<NBLOCKS, THREADS_A>>>(pm, ps, tg);
    cpl_finalize_kernel<<<1, THREADS_B>>>(out);
}

// round 12
// speedup vs baseline: 1.1101x; 1.1101x over previous
#include <cuda_runtime.h>

// ContrastivePredictionLoss — two-kernel, R12 (verbatim retry of R11 after
// broker/container infra failure — same flake pattern as R2/R7/R9, each of
// which passed unchanged on resubmission).
//
// Stage A: R6's proven 2048-block grid (1024-block single-wave variant REGRESSED
//          in R10: 34.7us vs 31.1us — surplus blocks win via load balancing).
//          Explicit 2-deep software pipeline in the stream loop — prefetch
//          next iteration's 3 float4 before consuming current, forcing >=6
//          LDG.128 in flight per thread at every consume point.
// Stage B: R6's cooperative float4 finalize verbatim (5.8us measured).

#define NB 64
#define ELEMS_PER_BATCH (4 * 256 * 256)      // 262144
#define BLOCKS_PER_BATCH 32
#define NBLOCKS (NB * BLOCKS_PER_BATCH)      // 2048
#define THREADS_A 256
#define ELEMS_PER_BLOCK (ELEMS_PER_BATCH / BLOCKS_PER_BATCH)   // 8192
#define VECS_PER_BLOCK (ELEMS_PER_BLOCK / 4)                   // 2048 float4
#define VECS_PER_THREAD (VECS_PER_BLOCK / THREADS_A)           // 8

// Scratch (allocation-free __device__ globals).
__device__ float g_part_err[NBLOCKS];
__device__ float g_part_unc[NBLOCKS];

__global__ __launch_bounds__(THREADS_A)
void cpl_reduce_kernel(const float4* __restrict__ pm,
                       const float4* __restrict__ ps,
                       const float4* __restrict__ tg) {
    const int blk = blockIdx.x;                      // b * 32 + chunk
    const int tid = threadIdx.x;
    const long base = (long)blk * VECS_PER_BLOCK + tid;

    float se = 0.0f;   // sum |pm - tg|
    float su = 0.0f;   // sum ps

    // 2-deep software pipeline: iteration i+1's loads are issued before
    // iteration i's values are consumed.
    float4 m0 = pm[base];
    float4 t0 = tg[base];
    float4 s0 = ps[base];

    #pragma unroll
    for (int i = 1; i < VECS_PER_THREAD; i++) {
        const long idx = base + (long)i * THREADS_A;
        float4 m1 = pm[idx];
        float4 t1 = tg[idx];
        float4 s1 = ps[idx];

        se += fabsf(m0.x - t0.x) + fabsf(m0.y - t0.y)
            + fabsf(m0.z - t0.z) + fabsf(m0.w - t0.w);
        su += s0.x + s0.y + s0.z + s0.w;

        m0 = m1; t0 = t1; s0 = s1;
    }
    se += fabsf(m0.x - t0.x) + fabsf(m0.y - t0.y)
        + fabsf(m0.z - t0.z) + fabsf(m0.w - t0.w);
    su += s0.x + s0.y + s0.z + s0.w;

    // Warp reduce (deterministic shuffle tree)
    #pragma unroll
    for (int off = 16; off > 0; off >>= 1) {
        se += __shfl_down_sync(0xFFFFFFFFu, se, off);
        su += __shfl_down_sync(0xFFFFFFFFu, su, off);
    }

    __shared__ float s_se[THREADS_A / 32];
    __shared__ float s_su[THREADS_A / 32];
    const int wid = tid >> 5;
    const int lid = tid & 31;
    if (lid == 0) { s_se[wid] = se; s_su[wid] = su; }
    __syncthreads();

    if (wid == 0) {
        se = (lid < THREADS_A / 32) ? s_se[lid] : 0.0f;
        su = (lid < THREADS_A / 32) ? s_su[lid] : 0.0f;
        #pragma unroll
        for (int off = 4; off > 0; off >>= 1) {
            se += __shfl_down_sync(0xFFFFFFFFu, se, off);
            su += __shfl_down_sync(0xFFFFFFFFu, su, off);
        }
        if (lid == 0) {
            g_part_err[blk] = se;
            g_part_unc[blk] = su;
        }
    }
}

#define THREADS_B 256

__global__ __launch_bounds__(THREADS_B)
void cpl_finalize_kernel(float* __restrict__ out) {
    const int tid = threadIdx.x;
    const int wid = tid >> 5;
    const int lid = tid & 31;

    // Cooperative vectorized load of partials:
    // 2048 floats per array = 512 float4. Thread tid -> batch b = tid>>2,
    // quarter q = tid&3. Each (b,q) loads 2 float4 = 8 consecutive partials
    // (batch b's 32 partials are float4 indices [b*8, b*8+8)).
    const int b = tid >> 2;
    const int q = tid & 3;
    const float4* pe4 = (const float4*)g_part_err;
    const float4* pu4 = (const float4*)g_part_unc;

    float4 e0 = pe4[b * 8 + q * 2 + 0];
    float4 e1 = pe4[b * 8 + q * 2 + 1];
    float4 u0 = pu4[b * 8 + q * 2 + 0];
    float4 u1 = pu4[b * 8 + q * 2 + 1];

    float pe = (e0.x + e0.y) + (e0.z + e0.w) + (e1.x + e1.y) + (e1.z + e1.w);
    float pu = (u0.x + u0.y) + (u0.z + u0.w) + (u1.x + u1.y) + (u1.z + u1.w);

    __shared__ float s_pe[4][NB];
    __shared__ float s_pu[4][NB];
    s_pe[q][b] = pe;
    s_pu[q][b] = pu;
    __syncthreads();

    __shared__ float errs[NB];
    __shared__ float uncs[NB];
    if (tid < NB) {
        const float inv = 1.0f / (float)ELEMS_PER_BATCH;
        errs[tid] = ((s_pe[0][tid] + s_pe[1][tid]) + (s_pe[2][tid] + s_pe[3][tid])) * inv;
        uncs[tid] = ((s_pu[0][tid] + s_pu[1][tid]) + (s_pu[2][tid] + s_pu[3][tid])) * inv;
    }
    __syncthreads();

    // Pairwise hinge over upper triangle (i < j), fixed iteration order.
    float acc = 0.0f;
    #pragma unroll
    for (int p = tid; p < NB * NB; p += THREADS_B) {
        const int i = p >> 6;
        const int j = p & 63;
        if (i < j) {
            const float d = ((errs[i] > errs[j]) ? (uncs[j] - uncs[i])
                                                 : (uncs[i] - uncs[j])) + 1.0f;
            acc += fmaxf(d, 0.0f);
        }
    }

    #pragma unroll
    for (int off = 16; off > 0; off >>= 1)
        acc += __shfl_down_sync(0xFFFFFFFFu, acc, off);

    __shared__ float s_acc[THREADS_B / 32];
    if (lid == 0) s_acc[wid] = acc;
    __syncthreads();

    if (tid == 0) {
        float total = 0.0f;
        #pragma unroll
        for (int w = 0; w < THREADS_B / 32; w++) total += s_acc[w];
        const int num_pairs = NB * (NB - 1) / 2;   // 2016
        out[0] = total / (float)num_pairs;
    }
}

extern "C" void kernel_launch(void* const* d_in, const int* in_sizes, int n_in,
                              void* d_out, int out_size) {
    const float4* pm = (const float4*)d_in[0];   // pred_mean
    const float4* ps = (const float4*)d_in[1];   // pred_std
    const float4* tg = (const float4*)d_in[2];   // targets
    float* out = (float*)d_out;

    cpl_reduce_kernel<<<NBLOCKS, THREADS_A>>>(pm, ps, tg);
    cpl_finalize_kernel<<<1, THREADS_B>>>(out);
}